// round 6
// baseline (speedup 1.0000x reference)
#include <cuda_runtime.h>
#include <cstdint>
#include <math.h>

// Pacemaker: OU process + Bernoulli spikes, bit-matching JAX threefry2x32
// (partitionable/fold-like semantics) + XLA erfinv.
// T=16384 steps, N=8192 neurons, out = f32 spikes [T, N].
//
// R5: fuse scan+spike into one warp-per-neuron kernel:
//  - kills the 1GB x round-trip
//  - 8192 warps of load parallelism (old scan had 256 warps, latency-bound)
//  - warp-coherent skip of the Bernoulli threefry (~46% of warps: p<=0 or p>=1
//    for all 32 consecutive t of a neuron, since OU x is time-correlated)

#define T_STEPS 16384
#define N_NEUR  8192

// per-step derived keys: (kn0, kn1, kb0, kb1)
__device__ uint4 g_keys[T_STEPS];
// noise scratch, NEURON-major: g_noise[i * T_STEPS + t]
__device__ __align__(16) float g_noise[(size_t)T_STEPS * N_NEUR];

// ---------------------------------------------------------------------------
// threefry2x32 (20 rounds) — identical to jax._src.prng.threefry2x32
// ---------------------------------------------------------------------------
__device__ __forceinline__ void tf_round4(uint32_t& x0, uint32_t& x1,
                                          int r0, int r1, int r2, int r3) {
  x0 += x1; x1 = __funnelshift_l(x1, x1, r0); x1 ^= x0;
  x0 += x1; x1 = __funnelshift_l(x1, x1, r1); x1 ^= x0;
  x0 += x1; x1 = __funnelshift_l(x1, x1, r2); x1 ^= x0;
  x0 += x1; x1 = __funnelshift_l(x1, x1, r3); x1 ^= x0;
}

__device__ __forceinline__ uint2 threefry2x32(uint32_t k0, uint32_t k1,
                                              uint32_t x0, uint32_t x1) {
  uint32_t ks2 = k0 ^ k1 ^ 0x1BD11BDAu;
  x0 += k0; x1 += k1;
  tf_round4(x0, x1, 13, 15, 26, 6);  x0 += k1;  x1 += ks2 + 1u;
  tf_round4(x0, x1, 17, 29, 16, 24); x0 += ks2; x1 += k0  + 2u;
  tf_round4(x0, x1, 13, 15, 26, 6);  x0 += k0;  x1 += k1  + 3u;
  tf_round4(x0, x1, 17, 29, 16, 24); x0 += k1;  x1 += ks2 + 4u;
  tf_round4(x0, x1, 13, 15, 26, 6);  x0 += ks2; x1 += k0  + 5u;
  return make_uint2(x0, x1);
}

// uniform [0,1): bitcast((bits>>9)|0x3f800000) - 1  (exact, matches jax)
__device__ __forceinline__ float u01_from_bits(uint32_t bits) {
  return __fsub_rn(__uint_as_float((bits >> 9) | 0x3f800000u), 1.0f);
}

// ---------------------------------------------------------------------------
// XLA ErfInv (f32, Giles coefficients). Separate mul/add (XLA does not form
// FMAs), log1pf == libdevice __nv_log1pf (what XLA:GPU lowers Log1p to).
// ---------------------------------------------------------------------------
__device__ __forceinline__ float erfinv_xla(float x) {
  float w = -log1pf(-__fmul_rn(x, x));
  float p;
  if (w < 5.0f) {
    w = __fadd_rn(w, -2.5f);
    p = 2.81022636e-08f;
    p = __fadd_rn(3.43273939e-07f,  __fmul_rn(p, w));
    p = __fadd_rn(-3.5233877e-06f,  __fmul_rn(p, w));
    p = __fadd_rn(-4.39150654e-06f, __fmul_rn(p, w));
    p = __fadd_rn(0.00021858087f,   __fmul_rn(p, w));
    p = __fadd_rn(-0.00125372503f,  __fmul_rn(p, w));
    p = __fadd_rn(-0.00417768164f,  __fmul_rn(p, w));
    p = __fadd_rn(0.246640727f,     __fmul_rn(p, w));
    p = __fadd_rn(1.50140941f,      __fmul_rn(p, w));
  } else {
    w = __fadd_rn(__fsqrt_rn(w), -3.0f);
    p = -0.000200214257f;
    p = __fadd_rn(0.000100950558f,  __fmul_rn(p, w));
    p = __fadd_rn(0.00134934322f,   __fmul_rn(p, w));
    p = __fadd_rn(-0.00367342844f,  __fmul_rn(p, w));
    p = __fadd_rn(0.00573950773f,   __fmul_rn(p, w));
    p = __fadd_rn(-0.0076224613f,   __fmul_rn(p, w));
    p = __fadd_rn(0.00943887047f,   __fmul_rn(p, w));
    p = __fadd_rn(1.00167406f,      __fmul_rn(p, w));
    p = __fadd_rn(2.83297682f,      __fmul_rn(p, w));
  }
  return __fmul_rn(p, x);
}

// ---------------------------------------------------------------------------
// K0: per-step key derivation.
// split(key(0), T)[t] = TF((0,0), (0,t)) ; kn = TF(kt,(0,0)) ; kb = TF(kt,(0,1))
// ---------------------------------------------------------------------------
__global__ void __launch_bounds__(256) k_keys() {
  int t = blockIdx.x * blockDim.x + threadIdx.x;
  if (t >= T_STEPS) return;
  uint2 kt = threefry2x32(0u, 0u, 0u, (uint32_t)t);
  uint2 kn = threefry2x32(kt.x, kt.y, 0u, 0u);
  uint2 kb = threefry2x32(kt.x, kt.y, 0u, 1u);
  g_keys[t] = make_uint4(kn.x, kn.y, kb.x, kb.y);
}

// ---------------------------------------------------------------------------
// K1: noise generation, parallel over (i, t). Thread = (one neuron i, 32
// consecutive t) -> writes one full 128B line of neuron-major g_noise.
// normal bits (partitionable): TF(kn_t, (0, i)).x ^ .y
// ---------------------------------------------------------------------------
__global__ void __launch_bounds__(256) k_noise() {
  __shared__ uint2 skn[32];
  const int IB = N_NEUR / 256;               // 32 i-blocks
  int iblk = blockIdx.x % IB;
  int tblk = blockIdx.x / IB;
  int i  = iblk * 256 + threadIdx.x;
  int t0 = tblk * 32;

  if (threadIdx.x < 32) {
    uint4 k = g_keys[t0 + threadIdx.x];
    skn[threadIdx.x] = make_uint2(k.x, k.y);
  }
  __syncthreads();

  const float LO  = __uint_as_float(0xBF7FFFFFu);   // nextafter(-1, 0)
  const float SQ2 = __uint_as_float(0x3FB504F3u);   // float(sqrt(2))
  const float NS  = (float)(0.6 * sqrt(0.001));     // sigma * sqrt(dt)

  float* dst = g_noise + (size_t)i * T_STEPS + t0;

  for (int jj = 0; jj < 32; jj += 4) {
    float tmp[4];
#pragma unroll
    for (int j = 0; j < 4; j++) {
      uint2 kn = skn[jj + j];
      uint2 r  = threefry2x32(kn.x, kn.y, 0u, (uint32_t)i);
      float f  = u01_from_bits(r.x ^ r.y);
      float u  = __fadd_rn(__fmul_rn(f, 2.0f), LO);  // uniform in [lo, 1)
      u = fmaxf(LO, u);
      tmp[j] = __fmul_rn(__fmul_rn(SQ2, erfinv_xla(u)), NS);
    }
    float4 o; o.x = tmp[0]; o.y = tmp[1]; o.z = tmp[2]; o.w = tmp[3];
    *reinterpret_cast<float4*>(dst + jj) = o;
  }
}

// ---------------------------------------------------------------------------
// K2 (fused): warp = 1 neuron; each chunk = 32 consecutive t.
//  lanes load 128B of neuron-major noise -> smem; lane0 runs the FP-exact
//  serial OU chain over the 32 values in-place; lanes read their x, ballot
//  on p = 0.003+x: if all lanes are <=0 or >=1, the Bernoulli threefry is
//  skipped (spike fully determined). Spikes go through a block smem tile so
//  the t-major stores stay sector-coalesced (8 consecutive neurons/row).
// ---------------------------------------------------------------------------
__global__ void __launch_bounds__(256) k_scan_spike(const float* __restrict__ state,
                                                    float* __restrict__ out) {
  __shared__ float buf[8][32];   // per-warp noise/x bounce (in-place rewrite)
  __shared__ float sp[8][33];    // per-warp spikes, padded vs bank conflicts

  const int w    = threadIdx.x >> 5;
  const int lane = threadIdx.x & 31;
  const int i    = blockIdx.x * 8 + w;
  const int i0   = blockIdx.x * 8;

  float x = state[i];            // meaningful in lane 0 only after chunk 0
  const float DT_F = 0.001f;
  const float RDT  = 0.003f;     // rate * dt
  const float* __restrict__ src = g_noise + (size_t)i * T_STEPS;

  // transposed-store coordinates (constant across chunks)
  const int tl = threadIdx.x >> 3;   // 0..31  (t within chunk)
  const int wl = threadIdx.x & 7;    // 0..7   (neuron within block)

  float n_cur = __ldcs(src + lane);

  for (int t0 = 0; t0 < T_STEPS; t0 += 32) {
    // prefetch next chunk's noise
    float n_next = 0.0f;
    if (t0 + 32 < T_STEPS) n_next = __ldcs(src + t0 + 32 + lane);

    buf[w][lane] = n_cur;
    __syncwarp();

    // lane 0: exact serial OU chain, in-place
    if (lane == 0) {
      float4 v[8];
#pragma unroll
      for (int j = 0; j < 8; j++)
        v[j] = *reinterpret_cast<const float4*>(&buf[w][j * 4]);
#pragma unroll
      for (int j = 0; j < 8; j++) {
        x = __fadd_rn(__fsub_rn(x, __fmul_rn(x, DT_F)), v[j].x); v[j].x = x;
        x = __fadd_rn(__fsub_rn(x, __fmul_rn(x, DT_F)), v[j].y); v[j].y = x;
        x = __fadd_rn(__fsub_rn(x, __fmul_rn(x, DT_F)), v[j].z); v[j].z = x;
        x = __fadd_rn(__fsub_rn(x, __fmul_rn(x, DT_F)), v[j].w); v[j].w = x;
      }
#pragma unroll
      for (int j = 0; j < 8; j++)
        *reinterpret_cast<float4*>(&buf[w][j * 4]) = v[j];
    }
    __syncwarp();

    float xl = buf[w][lane];
    float pr = __fadd_rn(RDT, xl);

    bool decided = (pr <= 0.0f) | (pr >= 1.0f);
    unsigned ball = __ballot_sync(0xffffffffu, decided);

    float s;
    if (ball == 0xffffffffu) {
      // whole warp determined: p<=0 -> u<p impossible (u>=0); p>=1 -> u<p always
      s = (pr >= 1.0f) ? 1.0f : 0.0f;
    } else {
      uint4 kk = g_keys[t0 + lane];
      uint2 r  = threefry2x32(kk.z, kk.w, 0u, (uint32_t)i);
      float u  = u01_from_bits(r.x ^ r.y);
      float pc = fminf(fmaxf(pr, 0.0f), 1.0f);   // jnp.clip
      s = (u < pc) ? 1.0f : 0.0f;
    }
    sp[w][lane] = s;
    __syncthreads();

    // block-cooperative transposed store: 256 threads cover 32t x 8i tile.
    // per warp: 4 rows x 8 consecutive floats = 4 aligned 32B sectors.
    out[(size_t)(t0 + tl) * N_NEUR + i0 + wl] = sp[wl][tl];
    __syncthreads();

    n_cur = n_next;
  }
}

// ---------------------------------------------------------------------------
// launch
// ---------------------------------------------------------------------------
extern "C" void kernel_launch(void* const* d_in, const int* in_sizes, int n_in,
                              void* d_out, int out_size) {
  const float* state = (const float*)d_in[0];   // zeros [N]
  float* out = (float*)d_out;                   // f32 [T*N]

  k_keys      <<<T_STEPS / 256, 256>>>();
  k_noise     <<<(N_NEUR / 256) * (T_STEPS / 32), 256>>>();
  k_scan_spike<<<N_NEUR / 8, 256>>>(state, out);
}

// round 7
// speedup vs baseline: 1.0230x; 1.0230x over previous
#include <cuda_runtime.h>
#include <cstdint>
#include <math.h>

// Pacemaker: OU process + Bernoulli spikes, bit-matching JAX threefry2x32
// (partitionable/fold-like semantics) + XLA erfinv.
// T=16384 steps, N=8192 neurons, out = f32 spikes [T, N].
//
// R6 structure:
//   k_keys : per-step keys -> g_kn (noise), g_kb (bernoulli)
//   k_noise: parallel noise gen, neuron-major g_noise[i][t]
//   k_scan : thread=neuron serial OU chain (FP-exact), prefetch depth 2,
//            writes x IN-PLACE over g_noise (neuron-major)
//   k_spike: warp=(neuron, 32 consecutive t); warp-coherent ballot skips the
//            Bernoulli threefry when all 32 p<=0 or p>=1 (~45% of chunks);
//            smem transpose -> coalesced t-major stores to d_out

#define T_STEPS 16384
#define N_NEUR  8192

__device__ uint2 g_kn[T_STEPS];
__device__ uint2 g_kb[T_STEPS];
// noise then x, NEURON-major: g_noise[i * T_STEPS + t]
__device__ __align__(16) float g_noise[(size_t)T_STEPS * N_NEUR];

// ---------------------------------------------------------------------------
// threefry2x32 (20 rounds) — identical to jax._src.prng.threefry2x32
// ---------------------------------------------------------------------------
__device__ __forceinline__ void tf_round4(uint32_t& x0, uint32_t& x1,
                                          int r0, int r1, int r2, int r3) {
  x0 += x1; x1 = __funnelshift_l(x1, x1, r0); x1 ^= x0;
  x0 += x1; x1 = __funnelshift_l(x1, x1, r1); x1 ^= x0;
  x0 += x1; x1 = __funnelshift_l(x1, x1, r2); x1 ^= x0;
  x0 += x1; x1 = __funnelshift_l(x1, x1, r3); x1 ^= x0;
}

__device__ __forceinline__ uint2 threefry2x32(uint32_t k0, uint32_t k1,
                                              uint32_t x0, uint32_t x1) {
  uint32_t ks2 = k0 ^ k1 ^ 0x1BD11BDAu;
  x0 += k0; x1 += k1;
  tf_round4(x0, x1, 13, 15, 26, 6);  x0 += k1;  x1 += ks2 + 1u;
  tf_round4(x0, x1, 17, 29, 16, 24); x0 += ks2; x1 += k0  + 2u;
  tf_round4(x0, x1, 13, 15, 26, 6);  x0 += k0;  x1 += k1  + 3u;
  tf_round4(x0, x1, 17, 29, 16, 24); x0 += k1;  x1 += ks2 + 4u;
  tf_round4(x0, x1, 13, 15, 26, 6);  x0 += ks2; x1 += k0  + 5u;
  return make_uint2(x0, x1);
}

// uniform [0,1): bitcast((bits>>9)|0x3f800000) - 1  (exact, matches jax)
__device__ __forceinline__ float u01_from_bits(uint32_t bits) {
  return __fsub_rn(__uint_as_float((bits >> 9) | 0x3f800000u), 1.0f);
}

// ---------------------------------------------------------------------------
// XLA ErfInv (f32, Giles). Separate mul/add (XLA does not form FMAs).
// ---------------------------------------------------------------------------
__device__ __forceinline__ float erfinv_xla(float x) {
  float w = -log1pf(-__fmul_rn(x, x));
  float p;
  if (w < 5.0f) {
    w = __fadd_rn(w, -2.5f);
    p = 2.81022636e-08f;
    p = __fadd_rn(3.43273939e-07f,  __fmul_rn(p, w));
    p = __fadd_rn(-3.5233877e-06f,  __fmul_rn(p, w));
    p = __fadd_rn(-4.39150654e-06f, __fmul_rn(p, w));
    p = __fadd_rn(0.00021858087f,   __fmul_rn(p, w));
    p = __fadd_rn(-0.00125372503f,  __fmul_rn(p, w));
    p = __fadd_rn(-0.00417768164f,  __fmul_rn(p, w));
    p = __fadd_rn(0.246640727f,     __fmul_rn(p, w));
    p = __fadd_rn(1.50140941f,      __fmul_rn(p, w));
  } else {
    w = __fadd_rn(__fsqrt_rn(w), -3.0f);
    p = -0.000200214257f;
    p = __fadd_rn(0.000100950558f,  __fmul_rn(p, w));
    p = __fadd_rn(0.00134934322f,   __fmul_rn(p, w));
    p = __fadd_rn(-0.00367342844f,  __fmul_rn(p, w));
    p = __fadd_rn(0.00573950773f,   __fmul_rn(p, w));
    p = __fadd_rn(-0.0076224613f,   __fmul_rn(p, w));
    p = __fadd_rn(0.00943887047f,   __fmul_rn(p, w));
    p = __fadd_rn(1.00167406f,      __fmul_rn(p, w));
    p = __fadd_rn(2.83297682f,      __fmul_rn(p, w));
  }
  return __fmul_rn(p, x);
}

// ---------------------------------------------------------------------------
// K0: per-step keys.
// split(key(0), T)[t] = TF((0,0),(0,t)); kn = TF(kt,(0,0)); kb = TF(kt,(0,1))
// ---------------------------------------------------------------------------
__global__ void __launch_bounds__(256) k_keys() {
  int t = blockIdx.x * blockDim.x + threadIdx.x;
  if (t >= T_STEPS) return;
  uint2 kt = threefry2x32(0u, 0u, 0u, (uint32_t)t);
  g_kn[t] = threefry2x32(kt.x, kt.y, 0u, 0u);
  g_kb[t] = threefry2x32(kt.x, kt.y, 0u, 1u);
}

// ---------------------------------------------------------------------------
// K1: noise gen. Thread = (neuron i, 32 consecutive t) -> writes one 128B
// line of neuron-major g_noise. bits = TF(kn_t, (0, i)).x ^ .y
// ---------------------------------------------------------------------------
__global__ void __launch_bounds__(256) k_noise() {
  __shared__ uint2 skn[32];
  const int IB = N_NEUR / 256;               // 32 i-blocks
  int iblk = blockIdx.x % IB;
  int tblk = blockIdx.x / IB;
  int i  = iblk * 256 + threadIdx.x;
  int t0 = tblk * 32;

  if (threadIdx.x < 32) skn[threadIdx.x] = g_kn[t0 + threadIdx.x];
  __syncthreads();

  const float LO  = __uint_as_float(0xBF7FFFFFu);   // nextafter(-1, 0)
  const float SQ2 = __uint_as_float(0x3FB504F3u);   // float(sqrt(2))
  const float NS  = (float)(0.6 * sqrt(0.001));     // sigma * sqrt(dt)

  float* dst = g_noise + (size_t)i * T_STEPS + t0;

  for (int jj = 0; jj < 32; jj += 4) {
    float tmp[4];
#pragma unroll
    for (int j = 0; j < 4; j++) {
      uint2 kn = skn[jj + j];
      uint2 r  = threefry2x32(kn.x, kn.y, 0u, (uint32_t)i);
      float f  = u01_from_bits(r.x ^ r.y);
      float u  = __fadd_rn(__fmul_rn(f, 2.0f), LO);
      u = fmaxf(LO, u);
      tmp[j] = __fmul_rn(__fmul_rn(SQ2, erfinv_xla(u)), NS);
    }
    float4 o; o.x = tmp[0]; o.y = tmp[1]; o.z = tmp[2]; o.w = tmp[3];
    *reinterpret_cast<float4*>(dst + jj) = o;
  }
}

// ---------------------------------------------------------------------------
// K2: serial OU scan per neuron (exact FP order). Thread = neuron.
// Prefetch depth 2 (16 LDG.128 in flight). Writes x IN-PLACE over g_noise
// (same thread owns the whole row -> no hazard; reads of chunk c+2 always
// precede the write of chunk c).
// ---------------------------------------------------------------------------
__global__ void __launch_bounds__(32) k_scan(const float* __restrict__ state) {
  const int i = blockIdx.x * 32 + threadIdx.x;
  float x = state[i];
  const float DT_F = 0.001f;

  float4* row = reinterpret_cast<float4*>(g_noise + (size_t)i * T_STEPS);
  const int NCH = T_STEPS / 32;   // 512 chunks of 8 float4

  float4 bufA[8], bufB[8];
#pragma unroll
  for (int j = 0; j < 8; j++) bufA[j] = __ldcs(&row[j]);
#pragma unroll
  for (int j = 0; j < 8; j++) bufB[j] = __ldcs(&row[8 + j]);

  for (int c = 0; c < NCH; c++) {
    // prefetch chunk c+2 (clamped; clamped loads are discarded)
    int pf = c + 2; if (pf > NCH - 1) pf = NCH - 1;
    float4 nx[8];
#pragma unroll
    for (int j = 0; j < 8; j++) nx[j] = __ldcs(&row[pf * 8 + j]);

    // process chunk c from bufA: exact chain, write x back in-place
#pragma unroll
    for (int j = 0; j < 8; j++) {
      float4 v = bufA[j];
      x = __fadd_rn(__fsub_rn(x, __fmul_rn(x, DT_F)), v.x); v.x = x;
      x = __fadd_rn(__fsub_rn(x, __fmul_rn(x, DT_F)), v.y); v.y = x;
      x = __fadd_rn(__fsub_rn(x, __fmul_rn(x, DT_F)), v.z); v.z = x;
      x = __fadd_rn(__fsub_rn(x, __fmul_rn(x, DT_F)), v.w); v.w = x;
      row[c * 8 + j] = v;
    }
#pragma unroll
    for (int j = 0; j < 8; j++) { bufA[j] = bufB[j]; bufB[j] = nx[j]; }
  }
}

// ---------------------------------------------------------------------------
// K3: spikes. Block = 256 threads = 8 warps; warp w handles neuron i0+w for
// 32 consecutive t (lane = t). Coherent ballot skips the threefry when the
// whole warp is decided (p<=0 -> 0, p>=1 -> 1). smem transpose gives
// coalesced t-major stores (8 consecutive neurons = aligned 32B sectors).
// ---------------------------------------------------------------------------
__global__ void __launch_bounds__(256) k_spike(float* __restrict__ out) {
  __shared__ float sp[8][33];

  const unsigned b  = blockIdx.x;
  const int i0   = (int)(b % (N_NEUR / 8)) * 8;
  const int t0   = (int)(b / (N_NEUR / 8)) * 32;
  const int w    = threadIdx.x >> 5;
  const int lane = threadIdx.x & 31;
  const int i    = i0 + w;

  const float RDT = 0.003f;   // rate * dt

  float xl = __ldcs(g_noise + (size_t)i * T_STEPS + t0 + lane);
  float pr = __fadd_rn(RDT, xl);

  bool decided = (pr <= 0.0f) | (pr >= 1.0f);
  unsigned ball = __ballot_sync(0xffffffffu, decided);

  float s;
  if (ball == 0xffffffffu) {
    s = (pr >= 1.0f) ? 1.0f : 0.0f;   // u in [0,1): p<=0 never fires, p>=1 always
  } else {
    uint2 kb = g_kb[t0 + lane];
    uint2 r  = threefry2x32(kb.x, kb.y, 0u, (uint32_t)i);
    float u  = u01_from_bits(r.x ^ r.y);
    float pc = fminf(fmaxf(pr, 0.0f), 1.0f);   // jnp.clip
    s = (u < pc) ? 1.0f : 0.0f;
  }
  sp[w][lane] = s;
  __syncthreads();

  // 256 threads cover the 32t x 8i tile; per warp: 4 rows x 8 consecutive
  // floats = 4 aligned 32B sectors.
  const int tl = threadIdx.x >> 3;   // 0..31 (t within chunk)
  const int wl = threadIdx.x & 7;    // 0..7  (neuron within group)
  out[(size_t)(t0 + tl) * N_NEUR + i0 + wl] = sp[wl][tl];
}

// ---------------------------------------------------------------------------
// launch
// ---------------------------------------------------------------------------
extern "C" void kernel_launch(void* const* d_in, const int* in_sizes, int n_in,
                              void* d_out, int out_size) {
  const float* state = (const float*)d_in[0];   // zeros [N]
  float* out = (float*)d_out;                   // f32 [T*N]

  k_keys <<<T_STEPS / 256, 256>>>();
  k_noise<<<(N_NEUR / 256) * (T_STEPS / 32), 256>>>();
  k_scan <<<N_NEUR / 32, 32>>>(state);
  k_spike<<<(N_NEUR / 8) * (T_STEPS / 32), 256>>>(out);
}

// round 8
// speedup vs baseline: 1.1798x; 1.1533x over previous
#include <cuda_runtime.h>
#include <cstdint>
#include <math.h>

// Pacemaker: OU process + Bernoulli spikes, bit-matching JAX threefry2x32
// (partitionable/fold-like semantics) + XLA erfinv.
// T=16384 steps, N=8192 neurons, out = f32 spikes [T, N].
//
// R7 structure (all arrays t-major -> every global access is warp-coalesced):
//   k_keys : per-step keys -> g_kn (noise), g_kb (bernoulli)
//   k_noise: parallel noise gen, T-MAJOR g_noise[t*N + i]
//   k_scan : thread=neuron serial OU chain (FP-exact); reads noise t-major
//            (1 line per LDG.32 per warp), writes x t-major into d_out
//   k_spike: R4 layout (thread = 4 consecutive neurons at one t), in-place
//            on d_out; measured at its ALU floor (alu=93%)

#define T_STEPS 16384
#define N_NEUR  8192

__device__ uint2 g_kn[T_STEPS];
__device__ uint2 g_kb[T_STEPS];
// noise, T-MAJOR: g_noise[t * N_NEUR + i]
__device__ __align__(16) float g_noise[(size_t)T_STEPS * N_NEUR];

// ---------------------------------------------------------------------------
// threefry2x32 (20 rounds) — identical to jax._src.prng.threefry2x32
// ---------------------------------------------------------------------------
__device__ __forceinline__ void tf_round4(uint32_t& x0, uint32_t& x1,
                                          int r0, int r1, int r2, int r3) {
  x0 += x1; x1 = __funnelshift_l(x1, x1, r0); x1 ^= x0;
  x0 += x1; x1 = __funnelshift_l(x1, x1, r1); x1 ^= x0;
  x0 += x1; x1 = __funnelshift_l(x1, x1, r2); x1 ^= x0;
  x0 += x1; x1 = __funnelshift_l(x1, x1, r3); x1 ^= x0;
}

__device__ __forceinline__ uint2 threefry2x32(uint32_t k0, uint32_t k1,
                                              uint32_t x0, uint32_t x1) {
  uint32_t ks2 = k0 ^ k1 ^ 0x1BD11BDAu;
  x0 += k0; x1 += k1;
  tf_round4(x0, x1, 13, 15, 26, 6);  x0 += k1;  x1 += ks2 + 1u;
  tf_round4(x0, x1, 17, 29, 16, 24); x0 += ks2; x1 += k0  + 2u;
  tf_round4(x0, x1, 13, 15, 26, 6);  x0 += k0;  x1 += k1  + 3u;
  tf_round4(x0, x1, 17, 29, 16, 24); x0 += k1;  x1 += ks2 + 4u;
  tf_round4(x0, x1, 13, 15, 26, 6);  x0 += ks2; x1 += k0  + 5u;
  return make_uint2(x0, x1);
}

// uniform [0,1): bitcast((bits>>9)|0x3f800000) - 1  (exact, matches jax)
__device__ __forceinline__ float u01_from_bits(uint32_t bits) {
  return __fsub_rn(__uint_as_float((bits >> 9) | 0x3f800000u), 1.0f);
}

// ---------------------------------------------------------------------------
// XLA ErfInv (f32, Giles). Separate mul/add (XLA does not form FMAs).
// ---------------------------------------------------------------------------
__device__ __forceinline__ float erfinv_xla(float x) {
  float w = -log1pf(-__fmul_rn(x, x));
  float p;
  if (w < 5.0f) {
    w = __fadd_rn(w, -2.5f);
    p = 2.81022636e-08f;
    p = __fadd_rn(3.43273939e-07f,  __fmul_rn(p, w));
    p = __fadd_rn(-3.5233877e-06f,  __fmul_rn(p, w));
    p = __fadd_rn(-4.39150654e-06f, __fmul_rn(p, w));
    p = __fadd_rn(0.00021858087f,   __fmul_rn(p, w));
    p = __fadd_rn(-0.00125372503f,  __fmul_rn(p, w));
    p = __fadd_rn(-0.00417768164f,  __fmul_rn(p, w));
    p = __fadd_rn(0.246640727f,     __fmul_rn(p, w));
    p = __fadd_rn(1.50140941f,      __fmul_rn(p, w));
  } else {
    w = __fadd_rn(__fsqrt_rn(w), -3.0f);
    p = -0.000200214257f;
    p = __fadd_rn(0.000100950558f,  __fmul_rn(p, w));
    p = __fadd_rn(0.00134934322f,   __fmul_rn(p, w));
    p = __fadd_rn(-0.00367342844f,  __fmul_rn(p, w));
    p = __fadd_rn(0.00573950773f,   __fmul_rn(p, w));
    p = __fadd_rn(-0.0076224613f,   __fmul_rn(p, w));
    p = __fadd_rn(0.00943887047f,   __fmul_rn(p, w));
    p = __fadd_rn(1.00167406f,      __fmul_rn(p, w));
    p = __fadd_rn(2.83297682f,      __fmul_rn(p, w));
  }
  return __fmul_rn(p, x);
}

// ---------------------------------------------------------------------------
// K0: per-step keys.
// split(key(0), T)[t] = TF((0,0),(0,t)); kn = TF(kt,(0,0)); kb = TF(kt,(0,1))
// ---------------------------------------------------------------------------
__global__ void __launch_bounds__(256) k_keys() {
  int t = blockIdx.x * blockDim.x + threadIdx.x;
  if (t >= T_STEPS) return;
  uint2 kt = threefry2x32(0u, 0u, 0u, (uint32_t)t);
  g_kn[t] = threefry2x32(kt.x, kt.y, 0u, 0u);
  g_kb[t] = threefry2x32(kt.x, kt.y, 0u, 1u);
}

// ---------------------------------------------------------------------------
// K1: noise gen, T-MAJOR output. Block = 8 warps; each warp owns one t
// (kn_t is warp-uniform -> broadcast load). Lane handles 4 consecutive
// neurons -> one fully-coalesced STG.128 (512B contiguous per warp).
// bits(t,i) = TF(kn_t, (0, i)).x ^ .y
// ---------------------------------------------------------------------------
__global__ void __launch_bounds__(256) k_noise() {
  const int IB = N_NEUR / 128;                 // 64 i-groups of 128 neurons
  const unsigned b = blockIdx.x;
  const int ib = (int)(b % IB);
  const int tb = (int)(b / IB);

  const int warp = threadIdx.x >> 5;
  const int lane = threadIdx.x & 31;
  const int t  = tb * 8 + warp;
  const int i0 = ib * 128 + lane * 4;

  uint2 kn = g_kn[t];                          // warp-uniform

  const float LO  = __uint_as_float(0xBF7FFFFFu);   // nextafter(-1, 0)
  const float SQ2 = __uint_as_float(0x3FB504F3u);   // float(sqrt(2))
  const float NS  = (float)(0.6 * sqrt(0.001));     // sigma * sqrt(dt)

  float tmp[4];
#pragma unroll
  for (int j = 0; j < 4; j++) {
    uint2 r = threefry2x32(kn.x, kn.y, 0u, (uint32_t)(i0 + j));
    float f = u01_from_bits(r.x ^ r.y);
    float u = __fadd_rn(__fmul_rn(f, 2.0f), LO);
    u = fmaxf(LO, u);
    tmp[j] = __fmul_rn(__fmul_rn(SQ2, erfinv_xla(u)), NS);
  }
  float4 o; o.x = tmp[0]; o.y = tmp[1]; o.z = tmp[2]; o.w = tmp[3];
  *reinterpret_cast<float4*>(g_noise + (size_t)t * N_NEUR + i0) = o;
}

// ---------------------------------------------------------------------------
// K2: serial OU scan (exact FP order). Thread = neuron, lane = consecutive i
// -> every LDG.32/STG.32 is one 128B line per warp (no wavefront blowup).
// Scalar double-buffer, prefetch distance 2 chunks (32 lines in flight).
// Writes x t-major into d_out (spike pass rewrites it in place).
// ---------------------------------------------------------------------------
__global__ void __launch_bounds__(32) k_scan(const float* __restrict__ state,
                                             float* __restrict__ xo) {
  const int i = blockIdx.x * 32 + threadIdx.x;
  float x = state[i];
  const float DT_F = 0.001f;
  const int NCH = T_STEPS / 32;                // 512 chunks of 32 steps

  const float* __restrict__ src = g_noise + i;
  float cur[32], nxt[32];

#pragma unroll
  for (int k = 0; k < 32; k++) cur[k] = __ldcs(src + (size_t)k * N_NEUR);
#pragma unroll
  for (int k = 0; k < 32; k++) nxt[k] = __ldcs(src + (size_t)(32 + k) * N_NEUR);

  for (int c = 0; c < NCH; c++) {
    int pc = c + 2; if (pc > NCH - 1) pc = NCH - 1;
    const float* ps = src + (size_t)pc * 32 * N_NEUR;
    float pf[32];
#pragma unroll
    for (int k = 0; k < 32; k++) pf[k] = __ldcs(ps + (size_t)k * N_NEUR);

    float* dst = xo + (size_t)c * 32 * N_NEUR + i;
#pragma unroll
    for (int k = 0; k < 32; k++) {
      x = __fadd_rn(__fsub_rn(x, __fmul_rn(x, DT_F)), cur[k]);
      dst[(size_t)k * N_NEUR] = x;
    }
#pragma unroll
    for (int k = 0; k < 32; k++) { cur[k] = nxt[k]; nxt[k] = pf[k]; }
  }
}

// ---------------------------------------------------------------------------
// K3: spikes (R4 layout — measured at ALU floor). Thread = 4 consecutive
// neurons at one t; in-place on d_out. u = TF(kb_t, (0,i)).x ^ .y
// ---------------------------------------------------------------------------
__global__ void __launch_bounds__(256) k_spike(float* __restrict__ xo) {
  unsigned tid = blockIdx.x * 256u + threadIdx.x;
  unsigned t   = tid / (N_NEUR / 4);
  unsigned i0  = (tid % (N_NEUR / 4)) * 4u;
  uint2 kb = g_kb[t];
  size_t base = (size_t)t * N_NEUR + i0;

  float4 xv = *reinterpret_cast<const float4*>(xo + base);
  const float RDT = 0.003f;   // rate * dt
  float xs[4] = {xv.x, xv.y, xv.z, xv.w};
  float sv[4];
#pragma unroll
  for (int j = 0; j < 4; j++) {
    uint2 r  = threefry2x32(kb.x, kb.y, 0u, i0 + (unsigned)j);
    float u  = u01_from_bits(r.x ^ r.y);
    float pr = __fadd_rn(RDT, xs[j]);
    pr = fminf(fmaxf(pr, 0.0f), 1.0f);   // jnp.clip
    sv[j] = (u < pr) ? 1.0f : 0.0f;
  }
  float4 s; s.x = sv[0]; s.y = sv[1]; s.z = sv[2]; s.w = sv[3];
  *reinterpret_cast<float4*>(xo + base) = s;
}

// ---------------------------------------------------------------------------
// launch
// ---------------------------------------------------------------------------
extern "C" void kernel_launch(void* const* d_in, const int* in_sizes, int n_in,
                              void* d_out, int out_size) {
  const float* state = (const float*)d_in[0];   // zeros [N]
  float* out = (float*)d_out;                   // f32 [T*N]

  k_keys <<<T_STEPS / 256, 256>>>();
  k_noise<<<(N_NEUR / 128) * (T_STEPS / 8), 256>>>();
  k_scan <<<N_NEUR / 32, 32>>>(state, out);
  k_spike<<<(unsigned)((size_t)T_STEPS * N_NEUR / 4 / 256), 256>>>(out);
}